// round 7
// baseline (speedup 1.0000x reference)
#include <cuda_runtime.h>

// HGCNLayer: KG scatter-mean + sparse user aggregation.
// Inputs (metadata order) — JAX default config: "int64" arrays are int32!
//  0: entity_emb     float32 [N_ENT * 128]
//  1: edge_index     int32   [2 * E]          (head row, then tail row)
//  2: edge_type      int32   [E]              (1-based relation id)
//  3: interact_rows  int32   [NNZ]
//  4: interact_cols  int32   [NNZ]
//  5: interact_vals  float32 [NNZ]
//  (optional slot: n_users scalar)
//  last: weight      float32 [R * 128]
// Output: [entity_agg (N_ENT*128) | user_agg (N_USR*128)] float32

#define DD 128
#define MAX_ENTITIES 100000

__device__ float g_counts[MAX_ENTITIES];

__device__ __forceinline__ void red_add_v4(float* p, float4 v) {
    asm volatile("red.global.add.v4.f32 [%0], {%1, %2, %3, %4};"
                 :: "l"(p), "f"(v.x), "f"(v.y), "f"(v.z), "f"(v.w)
                 : "memory");
}

// Zero the full output buffer (float4-wide) and the counts scratch.
__global__ void hgcn_zero_kernel(float4* __restrict__ out4, long n4, int n_ent) {
    long stride = (long)gridDim.x * blockDim.x;
    for (long i = (long)blockIdx.x * blockDim.x + threadIdx.x; i < n4; i += stride)
        out4[i] = make_float4(0.f, 0.f, 0.f, 0.f);
    for (long i = (long)blockIdx.x * blockDim.x + threadIdx.x; i < n_ent; i += stride)
        g_counts[i] = 0.f;
}

// One warp per edge: gather tail row, multiply by relation weight row,
// scatter-add (red.v4) into entity accumulator; lane 0 bumps the head count.
__global__ void hgcn_edge_kernel(const float* __restrict__ emb,
                                 const int* __restrict__ edge_index,
                                 const int* __restrict__ edge_type,
                                 const float* __restrict__ weight,
                                 float* __restrict__ ent_out,
                                 int n_edges) {
    int e = blockIdx.x * (blockDim.x >> 5) + (threadIdx.x >> 5);
    if (e >= n_edges) return;
    int lane = threadIdx.x & 31;

    int head = edge_index[e];
    int tail = edge_index[n_edges + e];
    int rel  = edge_type[e] - 1;

    const float4* trow = (const float4*)(emb + (long)tail * DD);
    const float4* wrow = (const float4*)(weight + (long)rel * DD);
    float4 a = __ldg(&trow[lane]);
    float4 b = __ldg(&wrow[lane]);
    float4 v = make_float4(a.x * b.x, a.y * b.y, a.z * b.z, a.w * b.w);

    red_add_v4(ent_out + (long)head * DD + lane * 4, v);
    if (lane == 0)
        atomicAdd(&g_counts[head], 1.0f);
}

// One warp per nnz: gather entity row, scale by val, scatter-add into user row.
__global__ void hgcn_user_kernel(const float* __restrict__ emb,
                                 const int* __restrict__ rows,
                                 const int* __restrict__ cols,
                                 const float* __restrict__ vals,
                                 float* __restrict__ user_out,
                                 int nnz) {
    int i = blockIdx.x * (blockDim.x >> 5) + (threadIdx.x >> 5);
    if (i >= nnz) return;
    int lane = threadIdx.x & 31;

    int u = rows[i];
    int c = cols[i];
    float s = vals[i];

    const float4* crow = (const float4*)(emb + (long)c * DD);
    float4 a = __ldg(&crow[lane]);
    float4 v = make_float4(a.x * s, a.y * s, a.z * s, a.w * s);

    red_add_v4(user_out + (long)u * DD + lane * 4, v);
}

// Divide each entity row by max(count, 1). Thread per float4.
__global__ void hgcn_finalize_kernel(float* __restrict__ ent_out, int n_ent) {
    long idx = (long)blockIdx.x * blockDim.x + threadIdx.x;  // float4 index
    long n4 = (long)n_ent * (DD / 4);
    if (idx >= n4) return;
    int row = (int)(idx >> 5);  // 32 float4 per row
    float c = g_counts[row];
    float inv = 1.0f / fmaxf(c, 1.0f);
    float4* p = (float4*)ent_out + idx;
    float4 v = *p;
    v.x *= inv; v.y *= inv; v.z *= inv; v.w *= inv;
    *p = v;
}

extern "C" void kernel_launch(void* const* d_in, const int* in_sizes, int n_in,
                              void* d_out, int out_size) {
    const float* emb    = (const float*)d_in[0];
    const int*   ei     = (const int*)d_in[1];
    const int*   et     = (const int*)d_in[2];
    const int*   irows  = (const int*)d_in[3];
    const int*   icols  = (const int*)d_in[4];
    const float* ivals  = (const float*)d_in[5];
    // weight is the LAST input regardless of whether the n_users scalar
    // occupies a slot.
    const float* weight = (const float*)d_in[n_in - 1];

    int n_entities = in_sizes[0] / DD;
    int n_edges    = in_sizes[2];
    int nnz        = in_sizes[5];

    float* ent_out  = (float*)d_out;
    float* user_out = (float*)d_out + (long)n_entities * DD;

    // 1) zero output + counts
    long n4 = (long)out_size / 4;
    {
        int threads = 256;
        int blocks = 2048;  // grid-stride
        hgcn_zero_kernel<<<blocks, threads>>>((float4*)d_out, n4, n_entities);
    }

    // 2) edge aggregation (warp per edge)
    {
        int threads = 256;                      // 8 warps/block
        int blocks = (n_edges + 7) / 8;
        hgcn_edge_kernel<<<blocks, threads>>>(emb, ei, et, weight, ent_out, n_edges);
    }

    // 3) user aggregation (warp per nnz)
    {
        int threads = 256;
        int blocks = (nnz + 7) / 8;
        hgcn_user_kernel<<<blocks, threads>>>(emb, irows, icols, ivals, user_out, nnz);
    }

    // 4) mean finalize
    {
        long n4e = (long)n_entities * (DD / 4);
        int threads = 256;
        int blocks = (int)((n4e + threads - 1) / threads);
        hgcn_finalize_kernel<<<blocks, threads>>>(ent_out, n_entities);
    }
}

// round 8
// speedup vs baseline: 1.0838x; 1.0838x over previous
#include <cuda_runtime.h>

// HGCNLayer: KG scatter-mean + sparse user aggregation.
// Inputs (JAX default config: "int64" arrays are int32):
//  0: entity_emb float32 [N_ENT*128], 1: edge_index int32 [2*E],
//  2: edge_type int32 [E], 3: interact_rows int32 [NNZ],
//  4: interact_cols int32 [NNZ], 5: interact_vals float32 [NNZ],
//  (optional n_users scalar), last: weight float32 [R*128]
// Output: [entity_agg (N_ENT*128) | user_agg (N_USR*128)] float32

#define DD 128
#define MAX_ENTITIES 100000
#define MAX_RELS 32

__device__ float g_counts[MAX_ENTITIES];

__device__ __forceinline__ void red_add_v4(float* p, float4 v) {
    asm volatile("red.global.add.v4.f32 [%0], {%1, %2, %3, %4};"
                 :: "l"(p), "f"(v.x), "f"(v.y), "f"(v.z), "f"(v.w)
                 : "memory");
}

// Zero the counts scratch (d_out is zeroed via cudaMemsetAsync).
__global__ void hgcn_zero_counts(int n_ent) {
    int i = blockIdx.x * blockDim.x + threadIdx.x;
    if (i < n_ent) g_counts[i] = 0.f;
}

// Two edges per warp. Relation weight table staged in smem (16 KB).
__global__ void hgcn_edge_kernel(const float* __restrict__ emb,
                                 const int* __restrict__ edge_index,
                                 const int* __restrict__ edge_type,
                                 const float* __restrict__ weight,
                                 float* __restrict__ ent_out,
                                 int n_edges, int n_rel) {
    __shared__ float4 sw[MAX_RELS * 32];  // [rel][lane] float4
    int nw4 = n_rel * 32;
    for (int i = threadIdx.x; i < nw4; i += blockDim.x)
        sw[i] = ((const float4*)weight)[i];
    __syncthreads();

    int warp = blockIdx.x * (blockDim.x >> 5) + (threadIdx.x >> 5);
    int lane = threadIdx.x & 31;
    int e0 = warp * 2;
    if (e0 >= n_edges) return;
    int e1 = e0 + 1;
    bool has1 = e1 < n_edges;

    int h0 = edge_index[e0];
    int t0 = edge_index[n_edges + e0];
    int r0 = edge_type[e0] - 1;
    int h1 = 0, t1 = 0, r1 = 0;
    if (has1) {
        h1 = edge_index[e1];
        t1 = edge_index[n_edges + e1];
        r1 = edge_type[e1] - 1;
    }

    // Issue both gathers back-to-back for MLP.
    float4 a0 = __ldg((const float4*)(emb + (long)t0 * DD) + lane);
    float4 a1 = make_float4(0.f, 0.f, 0.f, 0.f);
    if (has1) a1 = __ldg((const float4*)(emb + (long)t1 * DD) + lane);

    float4 b0 = sw[r0 * 32 + lane];
    float4 v0 = make_float4(a0.x * b0.x, a0.y * b0.y, a0.z * b0.z, a0.w * b0.w);
    red_add_v4(ent_out + (long)h0 * DD + lane * 4, v0);
    if (has1) {
        float4 b1 = sw[r1 * 32 + lane];
        float4 v1 = make_float4(a1.x * b1.x, a1.y * b1.y, a1.z * b1.z, a1.w * b1.w);
        red_add_v4(ent_out + (long)h1 * DD + lane * 4, v1);
    }
    if (lane == 0)  atomicAdd(&g_counts[h0], 1.0f);
    if (lane == 16 && has1) atomicAdd(&g_counts[h1], 1.0f);
}

// Two nnz per warp.
__global__ void hgcn_user_kernel(const float* __restrict__ emb,
                                 const int* __restrict__ rows,
                                 const int* __restrict__ cols,
                                 const float* __restrict__ vals,
                                 float* __restrict__ user_out,
                                 int nnz) {
    int warp = blockIdx.x * (blockDim.x >> 5) + (threadIdx.x >> 5);
    int lane = threadIdx.x & 31;
    int i0 = warp * 2;
    if (i0 >= nnz) return;
    int i1 = i0 + 1;
    bool has1 = i1 < nnz;

    int u0 = rows[i0], c0 = cols[i0];
    float s0 = vals[i0];
    int u1 = 0, c1 = 0;
    float s1 = 0.f;
    if (has1) { u1 = rows[i1]; c1 = cols[i1]; s1 = vals[i1]; }

    float4 a0 = __ldg((const float4*)(emb + (long)c0 * DD) + lane);
    float4 a1 = make_float4(0.f, 0.f, 0.f, 0.f);
    if (has1) a1 = __ldg((const float4*)(emb + (long)c1 * DD) + lane);

    float4 v0 = make_float4(a0.x * s0, a0.y * s0, a0.z * s0, a0.w * s0);
    red_add_v4(user_out + (long)u0 * DD + lane * 4, v0);
    if (has1) {
        float4 v1 = make_float4(a1.x * s1, a1.y * s1, a1.z * s1, a1.w * s1);
        red_add_v4(user_out + (long)u1 * DD + lane * 4, v1);
    }
}

// Divide each entity row by max(count, 1). Thread per float4.
__global__ void hgcn_finalize_kernel(float* __restrict__ ent_out, int n_ent) {
    long idx = (long)blockIdx.x * blockDim.x + threadIdx.x;
    long n4 = (long)n_ent * (DD / 4);
    if (idx >= n4) return;
    int row = (int)(idx >> 5);
    float inv = 1.0f / fmaxf(g_counts[row], 1.0f);
    float4* p = (float4*)ent_out + idx;
    float4 v = *p;
    v.x *= inv; v.y *= inv; v.z *= inv; v.w *= inv;
    *p = v;
}

extern "C" void kernel_launch(void* const* d_in, const int* in_sizes, int n_in,
                              void* d_out, int out_size) {
    const float* emb    = (const float*)d_in[0];
    const int*   ei     = (const int*)d_in[1];
    const int*   et     = (const int*)d_in[2];
    const int*   irows  = (const int*)d_in[3];
    const int*   icols  = (const int*)d_in[4];
    const float* ivals  = (const float*)d_in[5];
    const float* weight = (const float*)d_in[n_in - 1];

    int n_entities = in_sizes[0] / DD;
    int n_edges    = in_sizes[2];
    int nnz        = in_sizes[5];
    int n_rel      = in_sizes[n_in - 1] / DD;
    if (n_rel > MAX_RELS) n_rel = MAX_RELS;

    float* ent_out  = (float*)d_out;
    float* user_out = (float*)d_out + (long)n_entities * DD;

    // 1) zero output (DMA fill) + counts
    cudaMemsetAsync(d_out, 0, (size_t)out_size * sizeof(float));
    hgcn_zero_counts<<<(n_entities + 255) / 256, 256>>>(n_entities);

    // 2) edge aggregation (2 edges per warp, weight in smem)
    {
        int threads = 256;  // 8 warps -> 16 edges per block
        int blocks = (n_edges + 15) / 16;
        hgcn_edge_kernel<<<blocks, threads>>>(emb, ei, et, weight, ent_out,
                                              n_edges, n_rel);
    }

    // 3) user aggregation (2 nnz per warp)
    {
        int threads = 256;
        int blocks = (nnz + 15) / 16;
        hgcn_user_kernel<<<blocks, threads>>>(emb, irows, icols, ivals,
                                              user_out, nnz);
    }

    // 4) mean finalize
    {
        long n4e = (long)n_entities * (DD / 4);
        int threads = 256;
        int blocks = (int)((n4e + threads - 1) / threads);
        hgcn_finalize_kernel<<<blocks, threads>>>(ent_out, n_entities);
    }
}

// round 9
// speedup vs baseline: 1.1657x; 1.0755x over previous
#include <cuda_runtime.h>

// HGCNLayer: KG scatter-mean + sparse user aggregation.
// Inputs (JAX default config: "int64" arrays are int32):
//  0: entity_emb float32 [N_ENT*128], 1: edge_index int32 [2*E],
//  2: edge_type int32 [E], 3: interact_rows int32 [NNZ],
//  4: interact_cols int32 [NNZ], 5: interact_vals float32 [NNZ],
//  (optional n_users scalar), last: weight float32 [R*128]
// Output: [entity_agg (N_ENT*128) | user_agg (N_USR*128)] float32
//
// Strategy: counts-first. Pass 1 computes per-head edge counts; pass 2 inverts
// them; the fused scatter kernel multiplies each edge contribution by
// inv_count[head] before the red.v4, so no finalize read-modify-write pass
// over the 51 MB entity region is needed.

#define DD 128
#define MAX_ENTITIES 100000
#define MAX_RELS 32

__device__ float g_counts[MAX_ENTITIES];  // counts, then inverted in place

__device__ __forceinline__ void red_add_v4(float* p, float4 v) {
    asm volatile("red.global.add.v4.f32 [%0], {%1, %2, %3, %4};"
                 :: "l"(p), "f"(v.x), "f"(v.y), "f"(v.z), "f"(v.w)
                 : "memory");
}

__device__ __forceinline__ void red_add_f32(float* p, float v) {
    asm volatile("red.global.add.f32 [%0], %1;" :: "l"(p), "f"(v) : "memory");
}

// Pass 1: per-head edge counts (4 edges per thread for index-load efficiency).
__global__ void hgcn_count_kernel(const int* __restrict__ edge_index, int n_edges) {
    int base = (blockIdx.x * blockDim.x + threadIdx.x) * 4;
    #pragma unroll
    for (int j = 0; j < 4; j++) {
        int e = base + j;
        if (e < n_edges) red_add_f32(&g_counts[edge_index[e]], 1.0f);
    }
}

// Pass 2: counts -> 1/max(count,1), in place.
__global__ void hgcn_invert_kernel(int n_ent) {
    int i = blockIdx.x * blockDim.x + threadIdx.x;
    if (i < n_ent) g_counts[i] = 1.0f / fmaxf(g_counts[i], 1.0f);
}

// Fused scatter kernel. Blocks [0, edge_blocks) process edges (2 per warp,
// weight table staged in smem, contribution pre-scaled by inv count);
// remaining blocks process interactions (4 per warp).
__global__ void hgcn_scatter_kernel(const float* __restrict__ emb,
                                    const int* __restrict__ edge_index,
                                    const int* __restrict__ edge_type,
                                    const float* __restrict__ weight,
                                    const int* __restrict__ rows,
                                    const int* __restrict__ cols,
                                    const float* __restrict__ vals,
                                    float* __restrict__ ent_out,
                                    float* __restrict__ user_out,
                                    int n_edges, int n_rel, int nnz,
                                    int edge_blocks) {
    __shared__ float4 sw[MAX_RELS * 32];
    int lane = threadIdx.x & 31;
    int wib  = threadIdx.x >> 5;            // warp in block
    int wpb  = blockDim.x >> 5;             // warps per block

    if (blockIdx.x < edge_blocks) {
        // ---- edge half ----
        int nw4 = n_rel * 32;
        for (int i = threadIdx.x; i < nw4; i += blockDim.x)
            sw[i] = ((const float4*)weight)[i];
        __syncthreads();

        int warp = blockIdx.x * wpb + wib;
        int e0 = warp * 2;
        if (e0 >= n_edges) return;
        int e1 = e0 + 1;
        bool has1 = e1 < n_edges;

        int h0 = edge_index[e0];
        int t0 = edge_index[n_edges + e0];
        int r0 = edge_type[e0] - 1;
        int h1 = 0, t1 = 0, r1 = 0;
        if (has1) {
            h1 = edge_index[e1];
            t1 = edge_index[n_edges + e1];
            r1 = edge_type[e1] - 1;
        }

        float4 a0 = __ldg((const float4*)(emb + (long)t0 * DD) + lane);
        float4 a1 = make_float4(0.f, 0.f, 0.f, 0.f);
        if (has1) a1 = __ldg((const float4*)(emb + (long)t1 * DD) + lane);
        float inv0 = g_counts[h0];
        float inv1 = has1 ? g_counts[h1] : 0.f;

        float4 b0 = sw[r0 * 32 + lane];
        float4 v0 = make_float4(a0.x * b0.x * inv0, a0.y * b0.y * inv0,
                                a0.z * b0.z * inv0, a0.w * b0.w * inv0);
        red_add_v4(ent_out + (long)h0 * DD + lane * 4, v0);
        if (has1) {
            float4 b1 = sw[r1 * 32 + lane];
            float4 v1 = make_float4(a1.x * b1.x * inv1, a1.y * b1.y * inv1,
                                    a1.z * b1.z * inv1, a1.w * b1.w * inv1);
            red_add_v4(ent_out + (long)h1 * DD + lane * 4, v1);
        }
    } else {
        // ---- user half: 4 nnz per warp ----
        int warp = (blockIdx.x - edge_blocks) * wpb + wib;
        int base = warp * 4;
        if (base >= nnz) return;

        int   u[4], c[4];
        float s[4];
        int cnt = min(4, nnz - base);
        #pragma unroll
        for (int j = 0; j < 4; j++) {
            int i = base + ((j < cnt) ? j : 0);
            u[j] = rows[i]; c[j] = cols[i]; s[j] = vals[i];
        }

        float4 a[4];
        #pragma unroll
        for (int j = 0; j < 4; j++)
            a[j] = __ldg((const float4*)(emb + (long)c[j] * DD) + lane);

        #pragma unroll
        for (int j = 0; j < 4; j++) {
            if (j < cnt) {
                float4 v = make_float4(a[j].x * s[j], a[j].y * s[j],
                                       a[j].z * s[j], a[j].w * s[j]);
                red_add_v4(user_out + (long)u[j] * DD + lane * 4, v);
            }
        }
    }
}

extern "C" void kernel_launch(void* const* d_in, const int* in_sizes, int n_in,
                              void* d_out, int out_size) {
    const float* emb    = (const float*)d_in[0];
    const int*   ei     = (const int*)d_in[1];
    const int*   et     = (const int*)d_in[2];
    const int*   irows  = (const int*)d_in[3];
    const int*   icols  = (const int*)d_in[4];
    const float* ivals  = (const float*)d_in[5];
    const float* weight = (const float*)d_in[n_in - 1];

    int n_entities = in_sizes[0] / DD;
    int n_edges    = in_sizes[2];
    int nnz        = in_sizes[5];
    int n_rel      = in_sizes[n_in - 1] / DD;
    if (n_rel > MAX_RELS) n_rel = MAX_RELS;

    float* ent_out  = (float*)d_out;
    float* user_out = (float*)d_out + (long)n_entities * DD;

    // Zero output (DMA fill) and counts scratch.
    cudaMemsetAsync(d_out, 0, (size_t)out_size * sizeof(float));
    void* counts_addr = nullptr;
    cudaGetSymbolAddress(&counts_addr, g_counts);
    cudaMemsetAsync(counts_addr, 0, (size_t)n_entities * sizeof(float));

    // Pass 1: counts. Pass 2: invert.
    {
        int threads = 256;
        int per_block = threads * 4;
        hgcn_count_kernel<<<(n_edges + per_block - 1) / per_block, threads>>>(ei, n_edges);
        hgcn_invert_kernel<<<(n_entities + 255) / 256, 256>>>(n_entities);
    }

    // Fused scatter: edge blocks then user blocks in one grid.
    {
        int threads = 256;                         // 8 warps
        int edge_blocks = (n_edges + 15) / 16;     // 2 edges/warp
        int user_blocks = (nnz + 31) / 32;         // 4 nnz/warp
        hgcn_scatter_kernel<<<edge_blocks + user_blocks, threads>>>(
            emb, ei, et, weight, irows, icols, ivals,
            ent_out, user_out, n_edges, n_rel, nnz, edge_blocks);
    }
}